// round 14
// baseline (speedup 1.0000x reference)
#include <cuda_runtime.h>
#include <cuda_fp16.h>
#include <math.h>
#include <stdint.h>

// ---------------- problem constants ----------------
#define TOK   4096
#define EMB   1024
#define NH    16
#define HD    64
#define SEQ   2048
#define MLP   4096
#define LN_EPS 1e-5f
#define SM_SCL 0.18033688011112042f   // 0.125 * log2(e)

// ---------------- scratch ----------------
static __device__ __half g_h16 [(size_t)TOK * EMB];
static __device__ __half g_qkv16[(size_t)TOK * 3 * EMB];
static __device__ __half g_o16 [(size_t)TOK * EMB];
static __device__ __half g_act16[(size_t)TOK * MLP];
static __device__ float  g_x1  [(size_t)TOK * EMB];
static __device__ __half g_wq16[(size_t)EMB * 3 * EMB];
static __device__ __half g_wp16[(size_t)EMB * EMB];
static __device__ __half g_w116[(size_t)EMB * MLP];
static __device__ __half g_w216[(size_t)MLP * EMB];

// ---------------- helpers ----------------
__device__ __forceinline__ uint32_t smem_u32(const void* p) {
    uint32_t a;
    asm("{ .reg .u64 t; cvta.to.shared.u64 t, %1; cvt.u32.u64 %0, t; }" : "=r"(a) : "l"(p));
    return a;
}
__device__ __forceinline__ void sts128(uint32_t addr, uint4 v) {
    asm volatile("st.shared.v4.b32 [%0], {%1, %2, %3, %4};"
        :: "r"(addr), "r"(v.x), "r"(v.y), "r"(v.z), "r"(v.w));
}
__device__ __forceinline__ uint32_t h2u(__half2 h) { return *(uint32_t*)&h; }
// 128B rows: 16B chunk bits [4:7) ^= row&7
__device__ __forceinline__ uint32_t sw128(uint32_t off) {
    return off ^ ((off >> 3) & 0x70u);
}
// 256B rows
__device__ __forceinline__ uint32_t sw256(uint32_t off) {
    return off ^ (((off >> 8) & 7u) << 4);
}
__device__ __forceinline__ void ldsm_x4(uint32_t addr, uint32_t* r) {
    asm volatile("ldmatrix.sync.aligned.m8n8.x4.shared.b16 {%0,%1,%2,%3}, [%4];"
        : "=r"(r[0]), "=r"(r[1]), "=r"(r[2]), "=r"(r[3]) : "r"(addr));
}
__device__ __forceinline__ void ldsm_x4_t(uint32_t addr, uint32_t* r) {
    asm volatile("ldmatrix.sync.aligned.m8n8.x4.trans.shared.b16 {%0,%1,%2,%3}, [%4];"
        : "=r"(r[0]), "=r"(r[1]), "=r"(r[2]), "=r"(r[3]) : "r"(addr));
}
__device__ __forceinline__ void mma16816(float* d, const uint32_t* a, const uint32_t* b) {
    asm volatile("mma.sync.aligned.m16n8k16.row.col.f32.f16.f16.f32 "
        "{%0,%1,%2,%3}, {%4,%5,%6,%7}, {%8,%9}, {%0,%1,%2,%3};"
        : "+f"(d[0]), "+f"(d[1]), "+f"(d[2]), "+f"(d[3])
        : "r"(a[0]), "r"(a[1]), "r"(a[2]), "r"(a[3]), "r"(b[0]), "r"(b[1]));
}
__device__ __forceinline__ void cpasync16(uint32_t saddr, const void* g) {
    asm volatile("cp.async.cg.shared.global [%0], [%1], 16;" :: "r"(saddr), "l"(g));
}
#define CP_COMMIT() asm volatile("cp.async.commit_group;" ::: "memory")
#define CP_WAIT1()  asm volatile("cp.async.wait_group 1;" ::: "memory")
__device__ __forceinline__ float gelu_exact(float x) {
    return 0.5f * x * (1.f + erff(x * 0.70710678118654752f));
}

// ---------------- LayerNorm row body ----------------
__device__ __forceinline__ void ln_row(const float* __restrict__ x, __half* __restrict__ y,
                                       const float* __restrict__ gam,
                                       const float* __restrict__ bet, int tid)
{
    __shared__ float red[8], red2[8];
    __shared__ float s_mu, s_rstd;
    float4 v = *(const float4*)(x + tid * 4);
    float s  = v.x + v.y + v.z + v.w;
    float sq = v.x * v.x + v.y * v.y + v.z * v.z + v.w * v.w;
    const unsigned FULL = 0xffffffffu;
#pragma unroll
    for (int o = 16; o > 0; o >>= 1) {
        s  += __shfl_down_sync(FULL, s, o);
        sq += __shfl_down_sync(FULL, sq, o);
    }
    int warp = tid >> 5, lane = tid & 31;
    if (lane == 0) { red[warp] = s; red2[warp] = sq; }
    __syncthreads();
    if (warp == 0) {
        s  = (lane < 8) ? red[lane]  : 0.f;
        sq = (lane < 8) ? red2[lane] : 0.f;
#pragma unroll
        for (int o = 4; o > 0; o >>= 1) {
            s  += __shfl_down_sync(FULL, s, o);
            sq += __shfl_down_sync(FULL, sq, o);
        }
        if (lane == 0) {
            float mu = s * (1.f / EMB);
            float var = sq * (1.f / EMB) - mu * mu;
            s_mu = mu; s_rstd = rsqrtf(var + LN_EPS);
        }
    }
    __syncthreads();
    const float mu = s_mu, rstd = s_rstd;
    const float4 g4 = *(const float4*)(gam + tid * 4);
    const float4 b4 = *(const float4*)(bet + tid * 4);
    __half2 h0 = __floats2half2_rn((v.x - mu) * rstd * g4.x + b4.x,
                                   (v.y - mu) * rstd * g4.y + b4.y);
    __half2 h1 = __floats2half2_rn((v.z - mu) * rstd * g4.z + b4.z,
                                   (v.w - mu) * rstd * g4.w + b4.w);
    uint2 pk; pk.x = h2u(h0); pk.y = h2u(h1);
    *(uint2*)(y + tid * 4) = pk;
}

// =====================================================================
// prep: f2h of all 4 weights (blocks 0..6143) + LN1 (blocks 6144..10239)
// =====================================================================
__global__ void prep_kernel(const float* __restrict__ wq, __half* __restrict__ dq,
                            const float* __restrict__ wp, __half* __restrict__ dp,
                            const float* __restrict__ w1, __half* __restrict__ d1,
                            const float* __restrict__ w2, __half* __restrict__ d2,
                            const float* __restrict__ x,  __half* __restrict__ h16,
                            const float* __restrict__ g,  const float* __restrict__ bb)
{
    const int b = blockIdx.x;
    if (b >= 6144) {
        const int row = b - 6144;
        ln_row(x + (size_t)row * EMB, h16 + (size_t)row * EMB, g, bb, threadIdx.x);
        return;
    }
    const float* src; __half* dst; int rb;
    if (b < 1536)      { src = wq; dst = dq; rb = b; }
    else if (b < 2048) { src = wp; dst = dp; rb = b - 1536; }
    else if (b < 4096) { src = w1; dst = d1; rb = b - 2048; }
    else               { src = w2; dst = d2; rb = b - 4096; }
    const int i = (rb * 256 + threadIdx.x) * 8;
    float4 a = *(const float4*)(src + i);
    float4 c = *(const float4*)(src + i + 4);
    uint4 o;
    o.x = h2u(__floats2half2_rn(a.x, a.y));
    o.y = h2u(__floats2half2_rn(a.z, a.w));
    o.z = h2u(__floats2half2_rn(c.x, c.y));
    o.w = h2u(__floats2half2_rn(c.z, c.w));
    *(uint4*)(dst + i) = o;
}

__global__ void ln_kernel(const float* __restrict__ in, __half* __restrict__ out,
                          const float* __restrict__ gam, const float* __restrict__ bet)
{
    ln_row(in + (size_t)blockIdx.x * EMB, out + (size_t)blockIdx.x * EMB, gam, bet, threadIdx.x);
}

// =====================================================================
// HMMA GEMM v3: compile-time N/K, BK=64, 3-stage cp.async pipeline,
// prefetch issued BEFORE compute (distance 2), front-loaded ldsm per k-step.
// Block 128x128, 8 warps (2M x 4N) of 64x32.
// MODE: 0 = bias -> fp16, 1 = bias+gelu -> fp16, 2 = bias+res -> fp32
// =====================================================================
#define GEMM_SMEM (3 * 32768)

template<int MODE, int NN, int KK>
__global__ void __launch_bounds__(256, 2)
hgemm(const __half* __restrict__ A, const __half* __restrict__ B,
      const float* __restrict__ bias, const float* __restrict__ res,
      void* __restrict__ Cout)
{
    extern __shared__ char dsm[];
    const uint32_t base = smem_u32(dsm);

    const int tid  = threadIdx.x;
    const int lane = tid & 31, wid = tid >> 5;
    const int wm = (wid & 1) * 64;
    const int wn = (wid >> 1) * 32;
    const int bm = blockIdx.y * 128, bn = blockIdx.x * 128;
    const int g = lane >> 3;

    float acc[4][4][4];
#pragma unroll
    for (int i = 0; i < 4; ++i)
#pragma unroll
        for (int j = 0; j < 4; ++j)
#pragma unroll
            for (int c = 0; c < 4; ++c) acc[i][j][c] = 0.f;

    constexpr int nch = KK / 64;

    auto issue = [&](int buf, int kc) {
        const uint32_t sA = base + buf * 32768u;
        const uint32_t sB = sA + 16384u;
#pragma unroll
        for (int i = 0; i < 4; ++i) {
            const int cc = tid + i * 256;           // 0..1023
            const int rowa = cc >> 3, kch = cc & 7;
            cpasync16(sA + sw128((uint32_t)(rowa * 128 + kch * 16)),
                      A + (size_t)(bm + rowa) * KK + kc * 64 + kch * 8);
            const int rowb = cc >> 4, nch2 = cc & 15;
            cpasync16(sB + sw256((uint32_t)(rowb * 256 + nch2 * 16)),
                      B + (size_t)(kc * 64 + rowb) * NN + bn + nch2 * 8);
        }
    };

    auto compute = [&](int buf) {
        const uint32_t sA = base + buf * 32768u;
        const uint32_t sB = sA + 16384u;
#pragma unroll
        for (int ks = 0; ks < 4; ++ks) {
            uint32_t AF[4][4], BT[2][4];
            const int ra = wm + (g & 1) * 8 + (lane & 7);
            const int ca = ks * 32 + (g >> 1) * 16;
            const int rb = ks * 16 + (g & 1) * 8 + (lane & 7);
            // front-load all fragment ldsm for this k-step
#pragma unroll
            for (int mt = 0; mt < 4; ++mt)
                ldsm_x4(sA + sw128((uint32_t)((ra + mt * 16) * 128 + ca)), AF[mt]);
#pragma unroll
            for (int p = 0; p < 2; ++p) {
                const int cbb = (wn + p * 16) * 2 + (g >> 1) * 16;
                ldsm_x4_t(sB + sw256((uint32_t)(rb * 256 + cbb)), BT[p]);
            }
            // contiguous MMA burst
#pragma unroll
            for (int p = 0; p < 2; ++p)
#pragma unroll
                for (int mt = 0; mt < 4; ++mt) {
                    mma16816(acc[mt][p * 2 + 0], AF[mt], BT[p]);
                    mma16816(acc[mt][p * 2 + 1], AF[mt], BT[p] + 2);
                }
        }
    };

    issue(0, 0); CP_COMMIT();
    issue(1, 1); CP_COMMIT();

    int cur = 0;
    for (int kc = 0; kc < nch; ++kc) {
        CP_WAIT1();
        __syncthreads();
        // prefetch FIRST: stage (cur+2)%3 was computed last iteration, free now
        if (kc + 2 < nch) {
            int nxt = cur + 2; if (nxt >= 3) nxt -= 3;
            issue(nxt, kc + 2);
        }
        CP_COMMIT();
        compute(cur);
        if (++cur == 3) cur = 0;
    }

#pragma unroll
    for (int mt = 0; mt < 4; ++mt) {
#pragma unroll
        for (int nt = 0; nt < 4; ++nt) {
            const int col = bn + wn + nt * 8 + (lane & 3) * 2;
            const float b0 = bias[col], b1 = bias[col + 1];
#pragma unroll
            for (int dp = 0; dp < 2; ++dp) {
                const int row = bm + wm + mt * 16 + (lane >> 2) + dp * 8;
                float o0 = acc[mt][nt][dp * 2 + 0] + b0;
                float o1 = acc[mt][nt][dp * 2 + 1] + b1;
                if (MODE == 1) { o0 = gelu_exact(o0); o1 = gelu_exact(o1); }
                if (MODE == 2) {
                    const float2 rv = *(const float2*)(res + (size_t)row * NN + col);
                    float2 ov; ov.x = o0 + rv.x; ov.y = o1 + rv.y;
                    *(float2*)((float*)Cout + (size_t)row * NN + col) = ov;
                } else {
                    *(__half2*)((__half*)Cout + (size_t)row * NN + col) =
                        __floats2half2_rn(o0, o1);
                }
            }
        }
    }
}

// =====================================================================
// HMMA flash attention v3 (unchanged from R13)
// =====================================================================
#define ATT_SMEM (16384 + 2 * 16384)

__global__ void __launch_bounds__(256, 2)
attn_mma(const __half* __restrict__ qkv, __half* __restrict__ o)
{
    extern __shared__ char dynsm[];
    const uint32_t Qb = smem_u32(dynsm);

    const int tid  = threadIdx.x;
    const int lane = tid & 31, wid = tid >> 5;
    const int b = blockIdx.x >> 4, hh = blockIdx.x & 15;
    const int q0 = blockIdx.y * 128;
    const size_t tb = (size_t)b * SEQ;
    const size_t RS = 3 * EMB;
    const unsigned FULL = 0xffffffffu;
    const int g = lane >> 3;
    const uint32_t ONES[2] = {0x3C003C00u, 0x3C003C00u};

    auto issueKV = [&](int s, int kt) {
        const uint32_t Kb = Qb + 16384u + (uint32_t)s * 16384u;
        const uint32_t Vb = Kb + 8192u;
        const __half* kbase = qkv + (tb + kt * 64) * RS + EMB + hh * HD;
#pragma unroll
        for (int i = 0; i < 2; ++i) {
            const int cc = tid * 2 + i;
            const int r = cc >> 3, ch = cc & 7;
            const uint32_t off = sw128((uint32_t)(r * 128 + ch * 16));
            cpasync16(Kb + off, kbase + (size_t)r * RS + ch * 8);
            cpasync16(Vb + off, kbase + EMB + (size_t)r * RS + ch * 8);
        }
    };

    {
        const int r = tid >> 1, c0 = (tid & 1) * 32;
        const __half* qp = qkv + (tb + q0 + r) * RS + hh * HD + c0;
#pragma unroll
        for (int j = 0; j < 4; ++j)
            sts128(Qb + sw128((uint32_t)(r * 128 + (c0 + j * 8) * 2)),
                   *(const uint4*)(qp + j * 8));
    }
    issueKV(0, 0); CP_COMMIT();
    __syncthreads();

    uint32_t QF[4][4];
#pragma unroll
    for (int t = 0; t < 4; ++t) {
        const int r = wid * 16 + (g & 1) * 8 + (lane & 7);
        const int cb = t * 32 + (g >> 1) * 16;
        ldsm_x4(Qb + sw128((uint32_t)(r * 128 + cb)), QF[t]);
    }

    float Oa[8][4];
#pragma unroll
    for (int nt = 0; nt < 8; ++nt)
#pragma unroll
        for (int c = 0; c < 4; ++c) Oa[nt][c] = 0.f;
    float lacc[4] = {0.f, 0.f, 0.f, 0.f};
    float m_run[2] = {-INFINITY, -INFINITY};

    for (int kt = 0; kt < SEQ / 64; ++kt) {
        __syncthreads();
        if (kt + 1 < SEQ / 64) issueKV((kt + 1) & 1, kt + 1);
        CP_COMMIT();
        CP_WAIT1();
        __syncthreads();

        const uint32_t Kb = Qb + 16384u + (uint32_t)(kt & 1) * 16384u;
        const uint32_t Vb = Kb + 8192u;

        float sacc[8][4];
#pragma unroll
        for (int nt = 0; nt < 8; ++nt)
#pragma unroll
            for (int c = 0; c < 4; ++c) sacc[nt][c] = 0.f;

#pragma unroll
        for (int t = 0; t < 4; ++t) {
#pragma unroll
            for (int pr = 0; pr < 4; ++pr) {
                const int r = pr * 16 + (g >> 1) * 8 + (lane & 7);
                const int cb = t * 32 + (g & 1) * 16;
                uint32_t tt[4];
                ldsm_x4(Kb + sw128((uint32_t)(r * 128 + cb)), tt);
                mma16816(sacc[pr * 2 + 0], QF[t], tt);
                mma16816(sacc[pr * 2 + 1], QF[t], tt + 2);
            }
        }

        float fexp[2];
#pragma unroll
        for (int ri = 0; ri < 2; ++ri) {
            float mx = sacc[0][ri * 2];
#pragma unroll
            for (int nt = 0; nt < 8; ++nt) {
                mx = fmaxf(mx, sacc[nt][ri * 2]);
                mx = fmaxf(mx, sacc[nt][ri * 2 + 1]);
            }
            mx = fmaxf(mx, __shfl_xor_sync(FULL, mx, 1));
            mx = fmaxf(mx, __shfl_xor_sync(FULL, mx, 2));
            const float mn = fmaxf(m_run[ri], mx);
            fexp[ri] = exp2f((m_run[ri] - mn) * SM_SCL);
            m_run[ri] = mn;
        }
        const float negm0 = -m_run[0] * SM_SCL;
        const float negm1 = -m_run[1] * SM_SCL;

        uint32_t P0[8], P1[8];
#pragma unroll
        for (int nt = 0; nt < 8; ++nt) {
            __half2 d0 = __floats2half2_rn(fmaf(sacc[nt][0], SM_SCL, negm0),
                                           fmaf(sacc[nt][1], SM_SCL, negm0));
            __half2 d1 = __floats2half2_rn(fmaf(sacc[nt][2], SM_SCL, negm1),
                                           fmaf(sacc[nt][3], SM_SCL, negm1));
            P0[nt] = h2u(h2exp2(d0));
            P1[nt] = h2u(h2exp2(d1));
        }

#pragma unroll
        for (int nt = 0; nt < 8; ++nt)
#pragma unroll
            for (int c = 0; c < 4; ++c)
                Oa[nt][c] *= fexp[c >> 1];
        lacc[0] *= fexp[0]; lacc[1] *= fexp[0];
        lacc[2] *= fexp[1]; lacc[3] *= fexp[1];

#pragma unroll
        for (int k2 = 0; k2 < 4; ++k2) {
            uint32_t pa[4];
            pa[0] = P0[2 * k2];     pa[1] = P1[2 * k2];
            pa[2] = P0[2 * k2 + 1]; pa[3] = P1[2 * k2 + 1];
            mma16816(lacc, pa, ONES);
#pragma unroll
            for (int npr = 0; npr < 4; ++npr) {
                const int r = k2 * 16 + (g & 1) * 8 + (lane & 7);
                const int cb = npr * 32 + (g >> 1) * 16;
                uint32_t tt[4];
                ldsm_x4_t(Vb + sw128((uint32_t)(r * 128 + cb)), tt);
                mma16816(Oa[npr * 2 + 0], pa, tt);
                mma16816(Oa[npr * 2 + 1], pa, tt + 2);
            }
        }
    }

#pragma unroll
    for (int ri = 0; ri < 2; ++ri) {
        const int row = q0 + wid * 16 + ri * 8 + (lane >> 2);
        const float inv = 1.f / lacc[ri * 2];
#pragma unroll
        for (int nt = 0; nt < 8; ++nt) {
            const int col = nt * 8 + (lane & 3) * 2;
            *(__half2*)(o + (tb + row) * EMB + hh * HD + col) =
                __floats2half2_rn(Oa[nt][ri * 2 + 0] * inv,
                                  Oa[nt][ri * 2 + 1] * inv);
        }
    }
}

// ---------------- launch ----------------
extern "C" void kernel_launch(void* const* d_in, const int* in_sizes, int n_in,
                              void* d_out, int out_size)
{
    const float* x      = (const float*)d_in[0];
    const float* ln1_g  = (const float*)d_in[1];
    const float* ln1_b  = (const float*)d_in[2];
    const float* ln2_g  = (const float*)d_in[3];
    const float* ln2_b  = (const float*)d_in[4];
    const float* w_qkv  = (const float*)d_in[5];
    const float* b_qkv  = (const float*)d_in[6];
    const float* w_proj = (const float*)d_in[7];
    const float* b_proj = (const float*)d_in[8];
    const float* w_fc1  = (const float*)d_in[9];
    const float* b_fc1  = (const float*)d_in[10];
    const float* w_fc2  = (const float*)d_in[11];
    const float* b_fc2  = (const float*)d_in[12];
    float* out = (float*)d_out;

    void *p_h16, *p_qkv16, *p_o16, *p_act16, *p_x1;
    void *p_wq, *p_wp, *p_w1, *p_w2;
    cudaGetSymbolAddress(&p_h16, g_h16);
    cudaGetSymbolAddress(&p_qkv16, g_qkv16);
    cudaGetSymbolAddress(&p_o16, g_o16);
    cudaGetSymbolAddress(&p_act16, g_act16);
    cudaGetSymbolAddress(&p_x1, g_x1);
    cudaGetSymbolAddress(&p_wq, g_wq16);
    cudaGetSymbolAddress(&p_wp, g_wp16);
    cudaGetSymbolAddress(&p_w1, g_w116);
    cudaGetSymbolAddress(&p_w2, g_w216);
    __half* h16   = (__half*)p_h16;
    __half* qkv16 = (__half*)p_qkv16;
    __half* o16   = (__half*)p_o16;
    __half* act16 = (__half*)p_act16;
    float*  x1    = (float*)p_x1;
    __half* wq16  = (__half*)p_wq;
    __half* wp16  = (__half*)p_wp;
    __half* w116  = (__half*)p_w1;
    __half* w216  = (__half*)p_w2;

    cudaFuncSetAttribute((const void*)hgemm<0, 3 * EMB, EMB>,
                         cudaFuncAttributeMaxDynamicSharedMemorySize, GEMM_SMEM);
    cudaFuncSetAttribute((const void*)hgemm<2, EMB, EMB>,
                         cudaFuncAttributeMaxDynamicSharedMemorySize, GEMM_SMEM);
    cudaFuncSetAttribute((const void*)hgemm<1, MLP, EMB>,
                         cudaFuncAttributeMaxDynamicSharedMemorySize, GEMM_SMEM);
    cudaFuncSetAttribute((const void*)hgemm<2, EMB, MLP>,
                         cudaFuncAttributeMaxDynamicSharedMemorySize, GEMM_SMEM);
    cudaFuncSetAttribute(attn_mma, cudaFuncAttributeMaxDynamicSharedMemorySize, ATT_SMEM);

    // 0. weight f2h + LN1 in one launch
    prep_kernel<<<6144 + TOK, 256>>>(w_qkv, wq16, w_proj, wp16, w_fc1, w116,
                                     w_fc2, w216, x, h16, ln1_g, ln1_b);
    // 1. QKV (fp16 out)
    hgemm<0, 3 * EMB, EMB><<<dim3(3 * EMB / 128, TOK / 128), 256, GEMM_SMEM>>>(
        h16, wq16, b_qkv, nullptr, qkv16);
    // 2. attention (fp16 in/out)
    attn_mma<<<dim3(2 * NH, SEQ / 128), 256, ATT_SMEM>>>(qkv16, o16);
    // 3. proj + residual (fp32 out)
    hgemm<2, EMB, EMB><<<dim3(EMB / 128, TOK / 128), 256, GEMM_SMEM>>>(
        o16, wp16, b_proj, x, x1);
    // 4. LN2 -> h16
    ln_kernel<<<TOK, 256>>>(x1, h16, ln2_g, ln2_b);
    // 5. FC1 + GELU (fp16 out)
    hgemm<1, MLP, EMB><<<dim3(MLP / 128, TOK / 128), 256, GEMM_SMEM>>>(
        h16, w116, b_fc1, nullptr, act16);
    // 6. FC2 + residual (fp32 out)
    hgemm<2, EMB, MLP><<<dim3(EMB / 128, TOK / 128), 256, GEMM_SMEM>>>(
        act16, w216, b_fc2, x1, out);
}

// round 15
// speedup vs baseline: 1.0092x; 1.0092x over previous
#include <cuda_runtime.h>
#include <cuda_fp16.h>
#include <math.h>
#include <stdint.h>

// ---------------- problem constants ----------------
#define TOK   4096
#define EMB   1024
#define NH    16
#define HD    64
#define SEQ   2048
#define MLP   4096
#define LN_EPS 1e-5f
#define SM_SCL 0.18033688011112042f   // 0.125 * log2(e)

// ---------------- scratch ----------------
static __device__ __half g_h16 [(size_t)TOK * EMB];
static __device__ __half g_qkv16[(size_t)TOK * 3 * EMB];
static __device__ __half g_o16 [(size_t)TOK * EMB];
static __device__ __half g_act16[(size_t)TOK * MLP];
static __device__ float  g_x1  [(size_t)TOK * EMB];
static __device__ __half g_wq16[(size_t)EMB * 3 * EMB];
static __device__ __half g_wp16[(size_t)EMB * EMB];
static __device__ __half g_w116[(size_t)EMB * MLP];
static __device__ __half g_w216[(size_t)MLP * EMB];

// ---------------- helpers ----------------
__device__ __forceinline__ uint32_t smem_u32(const void* p) {
    uint32_t a;
    asm("{ .reg .u64 t; cvta.to.shared.u64 t, %1; cvt.u32.u64 %0, t; }" : "=r"(a) : "l"(p));
    return a;
}
__device__ __forceinline__ void sts128(uint32_t addr, uint4 v) {
    asm volatile("st.shared.v4.b32 [%0], {%1, %2, %3, %4};"
        :: "r"(addr), "r"(v.x), "r"(v.y), "r"(v.z), "r"(v.w));
}
__device__ __forceinline__ uint32_t h2u(__half2 h) { return *(uint32_t*)&h; }
// 128B rows: 16B chunk bits [4:7) ^= row&7
__device__ __forceinline__ uint32_t sw128(uint32_t off) {
    return off ^ ((off >> 3) & 0x70u);
}
// 256B rows
__device__ __forceinline__ uint32_t sw256(uint32_t off) {
    return off ^ (((off >> 8) & 7u) << 4);
}
__device__ __forceinline__ void ldsm_x4(uint32_t addr, uint32_t* r) {
    asm volatile("ldmatrix.sync.aligned.m8n8.x4.shared.b16 {%0,%1,%2,%3}, [%4];"
        : "=r"(r[0]), "=r"(r[1]), "=r"(r[2]), "=r"(r[3]) : "r"(addr));
}
__device__ __forceinline__ void ldsm_x4_t(uint32_t addr, uint32_t* r) {
    asm volatile("ldmatrix.sync.aligned.m8n8.x4.trans.shared.b16 {%0,%1,%2,%3}, [%4];"
        : "=r"(r[0]), "=r"(r[1]), "=r"(r[2]), "=r"(r[3]) : "r"(addr));
}
__device__ __forceinline__ void mma16816(float* d, const uint32_t* a, const uint32_t* b) {
    asm volatile("mma.sync.aligned.m16n8k16.row.col.f32.f16.f16.f32 "
        "{%0,%1,%2,%3}, {%4,%5,%6,%7}, {%8,%9}, {%0,%1,%2,%3};"
        : "+f"(d[0]), "+f"(d[1]), "+f"(d[2]), "+f"(d[3])
        : "r"(a[0]), "r"(a[1]), "r"(a[2]), "r"(a[3]), "r"(b[0]), "r"(b[1]));
}
__device__ __forceinline__ void cpasync16(uint32_t saddr, const void* g) {
    asm volatile("cp.async.cg.shared.global [%0], [%1], 16;" :: "r"(saddr), "l"(g));
}
#define CP_COMMIT() asm volatile("cp.async.commit_group;" ::: "memory")
#define CP_WAIT1()  asm volatile("cp.async.wait_group 1;" ::: "memory")
__device__ __forceinline__ float gelu_exact(float x) {
    return 0.5f * x * (1.f + erff(x * 0.70710678118654752f));
}

// ---------------- LayerNorm row body ----------------
__device__ __forceinline__ void ln_row(const float* __restrict__ x, __half* __restrict__ y,
                                       const float* __restrict__ gam,
                                       const float* __restrict__ bet, int tid)
{
    __shared__ float red[8], red2[8];
    __shared__ float s_mu, s_rstd;
    float4 v = *(const float4*)(x + tid * 4);
    float s  = v.x + v.y + v.z + v.w;
    float sq = v.x * v.x + v.y * v.y + v.z * v.z + v.w * v.w;
    const unsigned FULL = 0xffffffffu;
#pragma unroll
    for (int o = 16; o > 0; o >>= 1) {
        s  += __shfl_down_sync(FULL, s, o);
        sq += __shfl_down_sync(FULL, sq, o);
    }
    int warp = tid >> 5, lane = tid & 31;
    if (lane == 0) { red[warp] = s; red2[warp] = sq; }
    __syncthreads();
    if (warp == 0) {
        s  = (lane < 8) ? red[lane]  : 0.f;
        sq = (lane < 8) ? red2[lane] : 0.f;
#pragma unroll
        for (int o = 4; o > 0; o >>= 1) {
            s  += __shfl_down_sync(FULL, s, o);
            sq += __shfl_down_sync(FULL, sq, o);
        }
        if (lane == 0) {
            float mu = s * (1.f / EMB);
            float var = sq * (1.f / EMB) - mu * mu;
            s_mu = mu; s_rstd = rsqrtf(var + LN_EPS);
        }
    }
    __syncthreads();
    const float mu = s_mu, rstd = s_rstd;
    const float4 g4 = *(const float4*)(gam + tid * 4);
    const float4 b4 = *(const float4*)(bet + tid * 4);
    __half2 h0 = __floats2half2_rn((v.x - mu) * rstd * g4.x + b4.x,
                                   (v.y - mu) * rstd * g4.y + b4.y);
    __half2 h1 = __floats2half2_rn((v.z - mu) * rstd * g4.z + b4.z,
                                   (v.w - mu) * rstd * g4.w + b4.w);
    uint2 pk; pk.x = h2u(h0); pk.y = h2u(h1);
    *(uint2*)(y + tid * 4) = pk;
}

// =====================================================================
// prep: f2h of all 4 weights (blocks 0..6143) + LN1 (blocks 6144..10239)
// =====================================================================
__global__ void prep_kernel(const float* __restrict__ wq, __half* __restrict__ dq,
                            const float* __restrict__ wp, __half* __restrict__ dp,
                            const float* __restrict__ w1, __half* __restrict__ d1,
                            const float* __restrict__ w2, __half* __restrict__ d2,
                            const float* __restrict__ x,  __half* __restrict__ h16,
                            const float* __restrict__ g,  const float* __restrict__ bb)
{
    const int b = blockIdx.x;
    if (b >= 6144) {
        const int row = b - 6144;
        ln_row(x + (size_t)row * EMB, h16 + (size_t)row * EMB, g, bb, threadIdx.x);
        return;
    }
    const float* src; __half* dst; int rb;
    if (b < 1536)      { src = wq; dst = dq; rb = b; }
    else if (b < 2048) { src = wp; dst = dp; rb = b - 1536; }
    else if (b < 4096) { src = w1; dst = d1; rb = b - 2048; }
    else               { src = w2; dst = d2; rb = b - 4096; }
    const int i = (rb * 256 + threadIdx.x) * 8;
    float4 a = *(const float4*)(src + i);
    float4 c = *(const float4*)(src + i + 4);
    uint4 o;
    o.x = h2u(__floats2half2_rn(a.x, a.y));
    o.y = h2u(__floats2half2_rn(a.z, a.w));
    o.z = h2u(__floats2half2_rn(c.x, c.y));
    o.w = h2u(__floats2half2_rn(c.z, c.w));
    *(uint4*)(dst + i) = o;
}

__global__ void ln_kernel(const float* __restrict__ in, __half* __restrict__ out,
                          const float* __restrict__ gam, const float* __restrict__ bet)
{
    ln_row(in + (size_t)blockIdx.x * EMB, out + (size_t)blockIdx.x * EMB, gam, bet, threadIdx.x);
}

// =====================================================================
// HMMA GEMM (R13 schedule — measured best): compile-time N/K, BK=64,
// 3-stage cp.async pipeline, compute THEN issue.
// Block 128x128, 8 warps (2M x 4N) of 64x32.
// MODE: 0 = bias -> fp16, 1 = bias+gelu -> fp16, 2 = bias+res -> fp32
// =====================================================================
#define GEMM_SMEM (3 * 32768)

template<int MODE, int NN, int KK>
__global__ void __launch_bounds__(256, 2)
hgemm(const __half* __restrict__ A, const __half* __restrict__ B,
      const float* __restrict__ bias, const float* __restrict__ res,
      void* __restrict__ Cout)
{
    extern __shared__ char dsm[];
    const uint32_t base = smem_u32(dsm);

    const int tid  = threadIdx.x;
    const int lane = tid & 31, wid = tid >> 5;
    const int wm = (wid & 1) * 64;
    const int wn = (wid >> 1) * 32;
    const int bm = blockIdx.y * 128, bn = blockIdx.x * 128;
    const int g = lane >> 3;

    float acc[4][4][4];
#pragma unroll
    for (int i = 0; i < 4; ++i)
#pragma unroll
        for (int j = 0; j < 4; ++j)
#pragma unroll
            for (int c = 0; c < 4; ++c) acc[i][j][c] = 0.f;

    constexpr int nch = KK / 64;

    auto issue = [&](int buf, int kc) {
        const uint32_t sA = base + buf * 32768u;
        const uint32_t sB = sA + 16384u;
#pragma unroll
        for (int i = 0; i < 4; ++i) {
            const int cc = tid + i * 256;           // 0..1023
            const int rowa = cc >> 3, kch = cc & 7;
            cpasync16(sA + sw128((uint32_t)(rowa * 128 + kch * 16)),
                      A + (size_t)(bm + rowa) * KK + kc * 64 + kch * 8);
            const int rowb = cc >> 4, nch2 = cc & 15;
            cpasync16(sB + sw256((uint32_t)(rowb * 256 + nch2 * 16)),
                      B + (size_t)(kc * 64 + rowb) * NN + bn + nch2 * 8);
        }
    };

    auto compute = [&](int buf) {
        const uint32_t sA = base + buf * 32768u;
        const uint32_t sB = sA + 16384u;
#pragma unroll
        for (int ks = 0; ks < 4; ++ks) {
            uint32_t AF[4][4];
            const int ra = wm + (g & 1) * 8 + (lane & 7);
            const int ca = ks * 32 + (g >> 1) * 16;
#pragma unroll
            for (int mt = 0; mt < 4; ++mt)
                ldsm_x4(sA + sw128((uint32_t)((ra + mt * 16) * 128 + ca)), AF[mt]);
            const int rb = ks * 16 + (g & 1) * 8 + (lane & 7);
#pragma unroll
            for (int p = 0; p < 2; ++p) {
                uint32_t t[4];
                const int cbb = (wn + p * 16) * 2 + (g >> 1) * 16;
                ldsm_x4_t(sB + sw256((uint32_t)(rb * 256 + cbb)), t);
#pragma unroll
                for (int mt = 0; mt < 4; ++mt) {
                    mma16816(acc[mt][p * 2 + 0], AF[mt], t);
                    mma16816(acc[mt][p * 2 + 1], AF[mt], t + 2);
                }
            }
        }
    };

    issue(0, 0); CP_COMMIT();
    issue(1, 1); CP_COMMIT();

    int cur = 0;
    for (int kc = 0; kc < nch; ++kc) {
        CP_WAIT1();
        __syncthreads();
        compute(cur);
        if (kc + 2 < nch) {
            int nxt = cur + 2; if (nxt >= 3) nxt -= 3;
            issue(nxt, kc + 2);
        }
        CP_COMMIT();
        if (++cur == 3) cur = 0;
    }

#pragma unroll
    for (int mt = 0; mt < 4; ++mt) {
#pragma unroll
        for (int nt = 0; nt < 4; ++nt) {
            const int col = bn + wn + nt * 8 + (lane & 3) * 2;
            const float b0 = bias[col], b1 = bias[col + 1];
#pragma unroll
            for (int dp = 0; dp < 2; ++dp) {
                const int row = bm + wm + mt * 16 + (lane >> 2) + dp * 8;
                float o0 = acc[mt][nt][dp * 2 + 0] + b0;
                float o1 = acc[mt][nt][dp * 2 + 1] + b1;
                if (MODE == 1) { o0 = gelu_exact(o0); o1 = gelu_exact(o1); }
                if (MODE == 2) {
                    const float2 rv = *(const float2*)(res + (size_t)row * NN + col);
                    float2 ov; ov.x = o0 + rv.x; ov.y = o1 + rv.y;
                    *(float2*)((float*)Cout + (size_t)row * NN + col) = ov;
                } else {
                    *(__half2*)((__half*)Cout + (size_t)row * NN + col) =
                        __floats2half2_rn(o0, o1);
                }
            }
        }
    }
}

// =====================================================================
// HMMA flash attention v4: 3-stage K/V ring, ONE __syncthreads per tile.
// Warp owns 16 q-rows x all keys; key tile 64; base-2 f16x2 softmax;
// l via ones-MMA. smem: Q 16KB + 3 x (K 8KB + V 8KB) = 64KB; 2 CTAs/SM.
// =====================================================================
#define ATT_SMEM (16384 + 3 * 16384)

__global__ void __launch_bounds__(256, 2)
attn_mma(const __half* __restrict__ qkv, __half* __restrict__ o)
{
    extern __shared__ char dynsm[];
    const uint32_t Qb = smem_u32(dynsm);

    const int tid  = threadIdx.x;
    const int lane = tid & 31, wid = tid >> 5;
    const int b = blockIdx.x >> 4, hh = blockIdx.x & 15;
    const int q0 = blockIdx.y * 128;
    const size_t tb = (size_t)b * SEQ;
    const size_t RS = 3 * EMB;
    const unsigned FULL = 0xffffffffu;
    const int g = lane >> 3;
    const uint32_t ONES[2] = {0x3C003C00u, 0x3C003C00u};
    constexpr int NKT = SEQ / 64;

    auto issueKV = [&](int s, int kt) {
        const uint32_t Kb = Qb + 16384u + (uint32_t)s * 16384u;
        const uint32_t Vb = Kb + 8192u;
        const __half* kbase = qkv + (tb + kt * 64) * RS + EMB + hh * HD;
#pragma unroll
        for (int i = 0; i < 2; ++i) {
            const int cc = tid * 2 + i;
            const int r = cc >> 3, ch = cc & 7;
            const uint32_t off = sw128((uint32_t)(r * 128 + ch * 16));
            cpasync16(Kb + off, kbase + (size_t)r * RS + ch * 8);
            cpasync16(Vb + off, kbase + EMB + (size_t)r * RS + ch * 8);
        }
    };

    // ---- Q tile + prologue loads ----
    {
        const int r = tid >> 1, c0 = (tid & 1) * 32;
        const __half* qp = qkv + (tb + q0 + r) * RS + hh * HD + c0;
#pragma unroll
        for (int j = 0; j < 4; ++j)
            sts128(Qb + sw128((uint32_t)(r * 128 + (c0 + j * 8) * 2)),
                   *(const uint4*)(qp + j * 8));
    }
    issueKV(0, 0); CP_COMMIT();
    issueKV(1, 1); CP_COMMIT();
    __syncthreads();                    // Q visible

    uint32_t QF[4][4];
#pragma unroll
    for (int t = 0; t < 4; ++t) {
        const int r = wid * 16 + (g & 1) * 8 + (lane & 7);
        const int cb = t * 32 + (g >> 1) * 16;
        ldsm_x4(Qb + sw128((uint32_t)(r * 128 + cb)), QF[t]);
    }

    float Oa[8][4];
#pragma unroll
    for (int nt = 0; nt < 8; ++nt)
#pragma unroll
        for (int c = 0; c < 4; ++c) Oa[nt][c] = 0.f;
    float lacc[4] = {0.f, 0.f, 0.f, 0.f};
    float m_run[2] = {-INFINITY, -INFINITY};

    int cur = 0;
    for (int kt = 0; kt < NKT; ++kt) {
        CP_WAIT1();                      // group kt complete
        __syncthreads();                 // all warps done with stage computed at kt-1
        if (kt + 2 < NKT) {
            int nxt = cur + 2; if (nxt >= 3) nxt -= 3;
            issueKV(nxt, kt + 2);        // overwrites stage read at kt-1: safe
        }
        CP_COMMIT();

        const uint32_t Kb = Qb + 16384u + (uint32_t)cur * 16384u;
        const uint32_t Vb = Kb + 8192u;

        float sacc[8][4];
#pragma unroll
        for (int nt = 0; nt < 8; ++nt)
#pragma unroll
            for (int c = 0; c < 4; ++c) sacc[nt][c] = 0.f;

#pragma unroll
        for (int t = 0; t < 4; ++t) {
#pragma unroll
            for (int pr = 0; pr < 4; ++pr) {
                const int r = pr * 16 + (g >> 1) * 8 + (lane & 7);
                const int cb = t * 32 + (g & 1) * 16;
                uint32_t tt[4];
                ldsm_x4(Kb + sw128((uint32_t)(r * 128 + cb)), tt);
                mma16816(sacc[pr * 2 + 0], QF[t], tt);
                mma16816(sacc[pr * 2 + 1], QF[t], tt + 2);
            }
        }

        float fexp[2];
#pragma unroll
        for (int ri = 0; ri < 2; ++ri) {
            float mx = sacc[0][ri * 2];
#pragma unroll
            for (int nt = 0; nt < 8; ++nt) {
                mx = fmaxf(mx, sacc[nt][ri * 2]);
                mx = fmaxf(mx, sacc[nt][ri * 2 + 1]);
            }
            mx = fmaxf(mx, __shfl_xor_sync(FULL, mx, 1));
            mx = fmaxf(mx, __shfl_xor_sync(FULL, mx, 2));
            const float mn = fmaxf(m_run[ri], mx);
            fexp[ri] = exp2f((m_run[ri] - mn) * SM_SCL);
            m_run[ri] = mn;
        }
        const float negm0 = -m_run[0] * SM_SCL;
        const float negm1 = -m_run[1] * SM_SCL;

        uint32_t P0[8], P1[8];
#pragma unroll
        for (int nt = 0; nt < 8; ++nt) {
            __half2 d0 = __floats2half2_rn(fmaf(sacc[nt][0], SM_SCL, negm0),
                                           fmaf(sacc[nt][1], SM_SCL, negm0));
            __half2 d1 = __floats2half2_rn(fmaf(sacc[nt][2], SM_SCL, negm1),
                                           fmaf(sacc[nt][3], SM_SCL, negm1));
            P0[nt] = h2u(h2exp2(d0));
            P1[nt] = h2u(h2exp2(d1));
        }

#pragma unroll
        for (int nt = 0; nt < 8; ++nt)
#pragma unroll
            for (int c = 0; c < 4; ++c)
                Oa[nt][c] *= fexp[c >> 1];
        lacc[0] *= fexp[0]; lacc[1] *= fexp[0];
        lacc[2] *= fexp[1]; lacc[3] *= fexp[1];

#pragma unroll
        for (int k2 = 0; k2 < 4; ++k2) {
            uint32_t pa[4];
            pa[0] = P0[2 * k2];     pa[1] = P1[2 * k2];
            pa[2] = P0[2 * k2 + 1]; pa[3] = P1[2 * k2 + 1];
            mma16816(lacc, pa, ONES);
#pragma unroll
            for (int npr = 0; npr < 4; ++npr) {
                const int r = k2 * 16 + (g & 1) * 8 + (lane & 7);
                const int cb = npr * 32 + (g >> 1) * 16;
                uint32_t tt[4];
                ldsm_x4_t(Vb + sw128((uint32_t)(r * 128 + cb)), tt);
                mma16816(Oa[npr * 2 + 0], pa, tt);
                mma16816(Oa[npr * 2 + 1], pa, tt + 2);
            }
        }
        if (++cur == 3) cur = 0;
    }

#pragma unroll
    for (int ri = 0; ri < 2; ++ri) {
        const int row = q0 + wid * 16 + ri * 8 + (lane >> 2);
        const float inv = 1.f / lacc[ri * 2];
#pragma unroll
        for (int nt = 0; nt < 8; ++nt) {
            const int col = nt * 8 + (lane & 3) * 2;
            *(__half2*)(o + (tb + row) * EMB + hh * HD + col) =
                __floats2half2_rn(Oa[nt][ri * 2 + 0] * inv,
                                  Oa[nt][ri * 2 + 1] * inv);
        }
    }
}

// ---------------- launch ----------------
extern "C" void kernel_launch(void* const* d_in, const int* in_sizes, int n_in,
                              void* d_out, int out_size)
{
    const float* x      = (const float*)d_in[0];
    const float* ln1_g  = (const float*)d_in[1];
    const float* ln1_b  = (const float*)d_in[2];
    const float* ln2_g  = (const float*)d_in[3];
    const float* ln2_b  = (const float*)d_in[4];
    const float* w_qkv  = (const float*)d_in[5];
    const float* b_qkv  = (const float*)d_in[6];
    const float* w_proj = (const float*)d_in[7];
    const float* b_proj = (const float*)d_in[8];
    const float* w_fc1  = (const float*)d_in[9];
    const float* b_fc1  = (const float*)d_in[10];
    const float* w_fc2  = (const float*)d_in[11];
    const float* b_fc2  = (const float*)d_in[12];
    float* out = (float*)d_out;

    void *p_h16, *p_qkv16, *p_o16, *p_act16, *p_x1;
    void *p_wq, *p_wp, *p_w1, *p_w2;
    cudaGetSymbolAddress(&p_h16, g_h16);
    cudaGetSymbolAddress(&p_qkv16, g_qkv16);
    cudaGetSymbolAddress(&p_o16, g_o16);
    cudaGetSymbolAddress(&p_act16, g_act16);
    cudaGetSymbolAddress(&p_x1, g_x1);
    cudaGetSymbolAddress(&p_wq, g_wq16);
    cudaGetSymbolAddress(&p_wp, g_wp16);
    cudaGetSymbolAddress(&p_w1, g_w116);
    cudaGetSymbolAddress(&p_w2, g_w216);
    __half* h16   = (__half*)p_h16;
    __half* qkv16 = (__half*)p_qkv16;
    __half* o16   = (__half*)p_o16;
    __half* act16 = (__half*)p_act16;
    float*  x1    = (float*)p_x1;
    __half* wq16  = (__half*)p_wq;
    __half* wp16  = (__half*)p_wp;
    __half* w116  = (__half*)p_w1;
    __half* w216  = (__half*)p_w2;

    cudaFuncSetAttribute((const void*)hgemm<0, 3 * EMB, EMB>,
                         cudaFuncAttributeMaxDynamicSharedMemorySize, GEMM_SMEM);
    cudaFuncSetAttribute((const void*)hgemm<2, EMB, EMB>,
                         cudaFuncAttributeMaxDynamicSharedMemorySize, GEMM_SMEM);
    cudaFuncSetAttribute((const void*)hgemm<1, MLP, EMB>,
                         cudaFuncAttributeMaxDynamicSharedMemorySize, GEMM_SMEM);
    cudaFuncSetAttribute((const void*)hgemm<2, EMB, MLP>,
                         cudaFuncAttributeMaxDynamicSharedMemorySize, GEMM_SMEM);
    cudaFuncSetAttribute(attn_mma, cudaFuncAttributeMaxDynamicSharedMemorySize, ATT_SMEM);

    // 0. weight f2h + LN1 in one launch
    prep_kernel<<<6144 + TOK, 256>>>(w_qkv, wq16, w_proj, wp16, w_fc1, w116,
                                     w_fc2, w216, x, h16, ln1_g, ln1_b);
    // 1. QKV (fp16 out)
    hgemm<0, 3 * EMB, EMB><<<dim3(3 * EMB / 128, TOK / 128), 256, GEMM_SMEM>>>(
        h16, wq16, b_qkv, nullptr, qkv16);
    // 2. attention (fp16 in/out)
    attn_mma<<<dim3(2 * NH, SEQ / 128), 256, ATT_SMEM>>>(qkv16, o16);
    // 3. proj + residual (fp32 out)
    hgemm<2, EMB, EMB><<<dim3(EMB / 128, TOK / 128), 256, GEMM_SMEM>>>(
        o16, wp16, b_proj, x, x1);
    // 4. LN2 -> h16
    ln_kernel<<<TOK, 256>>>(x1, h16, ln2_g, ln2_b);
    // 5. FC1 + GELU (fp16 out)
    hgemm<1, MLP, EMB><<<dim3(MLP / 128, TOK / 128), 256, GEMM_SMEM>>>(
        h16, w116, b_fc1, nullptr, act16);
    // 6. FC2 + residual (fp32 out)
    hgemm<2, EMB, MLP><<<dim3(EMB / 128, TOK / 128), 256, GEMM_SMEM>>>(
        act16, w216, b_fc2, x1, out);
}

// round 16
// speedup vs baseline: 1.0274x; 1.0181x over previous
#include <cuda_runtime.h>
#include <cuda_fp16.h>
#include <math.h>
#include <stdint.h>

// ---------------- problem constants ----------------
#define TOK   4096
#define EMB   1024
#define NH    16
#define HD    64
#define SEQ   2048
#define MLP   4096
#define LN_EPS 1e-5f
#define SM_SCL 0.18033688011112042f   // 0.125 * log2(e)

// ---------------- scratch ----------------
static __device__ __half g_h16 [(size_t)TOK * EMB];
static __device__ __half g_qkv16[(size_t)TOK * 3 * EMB];
static __device__ __half g_o16 [(size_t)TOK * EMB];
static __device__ __half g_act16[(size_t)TOK * MLP];
static __device__ float  g_x1  [(size_t)TOK * EMB];
static __device__ __half g_wq16[(size_t)EMB * 3 * EMB];
static __device__ __half g_wp16[(size_t)EMB * EMB];
static __device__ __half g_w116[(size_t)EMB * MLP];
static __device__ __half g_w216[(size_t)MLP * EMB];

// ---------------- helpers ----------------
__device__ __forceinline__ uint32_t smem_u32(const void* p) {
    uint32_t a;
    asm("{ .reg .u64 t; cvta.to.shared.u64 t, %1; cvt.u32.u64 %0, t; }" : "=r"(a) : "l"(p));
    return a;
}
__device__ __forceinline__ void sts128(uint32_t addr, uint4 v) {
    asm volatile("st.shared.v4.b32 [%0], {%1, %2, %3, %4};"
        :: "r"(addr), "r"(v.x), "r"(v.y), "r"(v.z), "r"(v.w));
}
__device__ __forceinline__ uint32_t h2u(__half2 h) { return *(uint32_t*)&h; }
// 128B rows: 16B chunk bits [4:7) ^= row&7
__device__ __forceinline__ uint32_t sw128(uint32_t off) {
    return off ^ ((off >> 3) & 0x70u);
}
// 256B rows
__device__ __forceinline__ uint32_t sw256(uint32_t off) {
    return off ^ (((off >> 8) & 7u) << 4);
}
__device__ __forceinline__ void ldsm_x4(uint32_t addr, uint32_t* r) {
    asm volatile("ldmatrix.sync.aligned.m8n8.x4.shared.b16 {%0,%1,%2,%3}, [%4];"
        : "=r"(r[0]), "=r"(r[1]), "=r"(r[2]), "=r"(r[3]) : "r"(addr));
}
__device__ __forceinline__ void ldsm_x4_t(uint32_t addr, uint32_t* r) {
    asm volatile("ldmatrix.sync.aligned.m8n8.x4.trans.shared.b16 {%0,%1,%2,%3}, [%4];"
        : "=r"(r[0]), "=r"(r[1]), "=r"(r[2]), "=r"(r[3]) : "r"(addr));
}
__device__ __forceinline__ void mma16816(float* d, const uint32_t* a, const uint32_t* b) {
    asm volatile("mma.sync.aligned.m16n8k16.row.col.f32.f16.f16.f32 "
        "{%0,%1,%2,%3}, {%4,%5,%6,%7}, {%8,%9}, {%0,%1,%2,%3};"
        : "+f"(d[0]), "+f"(d[1]), "+f"(d[2]), "+f"(d[3])
        : "r"(a[0]), "r"(a[1]), "r"(a[2]), "r"(a[3]), "r"(b[0]), "r"(b[1]));
}
__device__ __forceinline__ void cpasync16(uint32_t saddr, const void* g) {
    asm volatile("cp.async.cg.shared.global [%0], [%1], 16;" :: "r"(saddr), "l"(g));
}
#define CP_COMMIT() asm volatile("cp.async.commit_group;" ::: "memory")
#define CP_WAIT1()  asm volatile("cp.async.wait_group 1;" ::: "memory")
__device__ __forceinline__ float gelu_exact(float x) {
    return 0.5f * x * (1.f + erff(x * 0.70710678118654752f));
}

// ---------------- fp32->fp16 convert block (2048 elems/block) ----------------
__device__ __forceinline__ void f2h_block(const float* __restrict__ src,
                                          __half* __restrict__ dst, int rb, int tid)
{
    const int i = (rb * 256 + tid) * 8;
    float4 a = *(const float4*)(src + i);
    float4 c = *(const float4*)(src + i + 4);
    uint4 o;
    o.x = h2u(__floats2half2_rn(a.x, a.y));
    o.y = h2u(__floats2half2_rn(a.z, a.w));
    o.z = h2u(__floats2half2_rn(c.x, c.y));
    o.w = h2u(__floats2half2_rn(c.z, c.w));
    *(uint4*)(dst + i) = o;
}

// ---------------- LayerNorm row body ----------------
__device__ __forceinline__ void ln_row(const float* __restrict__ x, __half* __restrict__ y,
                                       const float* __restrict__ gam,
                                       const float* __restrict__ bet, int tid)
{
    __shared__ float red[8], red2[8];
    __shared__ float s_mu, s_rstd;
    float4 v = *(const float4*)(x + tid * 4);
    float s  = v.x + v.y + v.z + v.w;
    float sq = v.x * v.x + v.y * v.y + v.z * v.z + v.w * v.w;
    const unsigned FULL = 0xffffffffu;
#pragma unroll
    for (int o = 16; o > 0; o >>= 1) {
        s  += __shfl_down_sync(FULL, s, o);
        sq += __shfl_down_sync(FULL, sq, o);
    }
    int warp = tid >> 5, lane = tid & 31;
    if (lane == 0) { red[warp] = s; red2[warp] = sq; }
    __syncthreads();
    if (warp == 0) {
        s  = (lane < 8) ? red[lane]  : 0.f;
        sq = (lane < 8) ? red2[lane] : 0.f;
#pragma unroll
        for (int o = 4; o > 0; o >>= 1) {
            s  += __shfl_down_sync(FULL, s, o);
            sq += __shfl_down_sync(FULL, sq, o);
        }
        if (lane == 0) {
            float mu = s * (1.f / EMB);
            float var = sq * (1.f / EMB) - mu * mu;
            s_mu = mu; s_rstd = rsqrtf(var + LN_EPS);
        }
    }
    __syncthreads();
    const float mu = s_mu, rstd = s_rstd;
    const float4 g4 = *(const float4*)(gam + tid * 4);
    const float4 b4 = *(const float4*)(bet + tid * 4);
    __half2 h0 = __floats2half2_rn((v.x - mu) * rstd * g4.x + b4.x,
                                   (v.y - mu) * rstd * g4.y + b4.y);
    __half2 h1 = __floats2half2_rn((v.z - mu) * rstd * g4.z + b4.z,
                                   (v.w - mu) * rstd * g4.w + b4.w);
    uint2 pk; pk.x = h2u(h0); pk.y = h2u(h1);
    *(uint2*)(y + tid * 4) = pk;
}

// =====================================================================
// prep: wq f2h (blocks 0..1535) + LN1 (blocks 1536..5631)
// (wp/w1/w2 conversion is deferred into the attention launch)
// =====================================================================
__global__ void prep_kernel(const float* __restrict__ wq, __half* __restrict__ dq,
                            const float* __restrict__ x,  __half* __restrict__ h16,
                            const float* __restrict__ g,  const float* __restrict__ bb)
{
    const int b = blockIdx.x;
    if (b >= 1536) {
        const int row = b - 1536;
        ln_row(x + (size_t)row * EMB, h16 + (size_t)row * EMB, g, bb, threadIdx.x);
        return;
    }
    f2h_block(wq, dq, b, threadIdx.x);
}

__global__ void ln_kernel(const float* __restrict__ in, __half* __restrict__ out,
                          const float* __restrict__ gam, const float* __restrict__ bet)
{
    ln_row(in + (size_t)blockIdx.x * EMB, out + (size_t)blockIdx.x * EMB, gam, bet, threadIdx.x);
}

// =====================================================================
// HMMA GEMM (R13/R15 schedule — measured best): compile-time N/K, BK=64,
// 3-stage cp.async pipeline, compute THEN issue.
// Block 128x128, 8 warps (2M x 4N) of 64x32.
// MODE: 0 = bias -> fp16, 1 = bias+gelu -> fp16, 2 = bias+res -> fp32
// =====================================================================
#define GEMM_SMEM (3 * 32768)

template<int MODE, int NN, int KK>
__global__ void __launch_bounds__(256, 2)
hgemm(const __half* __restrict__ A, const __half* __restrict__ B,
      const float* __restrict__ bias, const float* __restrict__ res,
      void* __restrict__ Cout)
{
    extern __shared__ char dsm[];
    const uint32_t base = smem_u32(dsm);

    const int tid  = threadIdx.x;
    const int lane = tid & 31, wid = tid >> 5;
    const int wm = (wid & 1) * 64;
    const int wn = (wid >> 1) * 32;
    const int bm = blockIdx.y * 128, bn = blockIdx.x * 128;
    const int g = lane >> 3;

    float acc[4][4][4];
#pragma unroll
    for (int i = 0; i < 4; ++i)
#pragma unroll
        for (int j = 0; j < 4; ++j)
#pragma unroll
            for (int c = 0; c < 4; ++c) acc[i][j][c] = 0.f;

    constexpr int nch = KK / 64;

    auto issue = [&](int buf, int kc) {
        const uint32_t sA = base + buf * 32768u;
        const uint32_t sB = sA + 16384u;
#pragma unroll
        for (int i = 0; i < 4; ++i) {
            const int cc = tid + i * 256;           // 0..1023
            const int rowa = cc >> 3, kch = cc & 7;
            cpasync16(sA + sw128((uint32_t)(rowa * 128 + kch * 16)),
                      A + (size_t)(bm + rowa) * KK + kc * 64 + kch * 8);
            const int rowb = cc >> 4, nch2 = cc & 15;
            cpasync16(sB + sw256((uint32_t)(rowb * 256 + nch2 * 16)),
                      B + (size_t)(kc * 64 + rowb) * NN + bn + nch2 * 8);
        }
    };

    auto compute = [&](int buf) {
        const uint32_t sA = base + buf * 32768u;
        const uint32_t sB = sA + 16384u;
#pragma unroll
        for (int ks = 0; ks < 4; ++ks) {
            uint32_t AF[4][4];
            const int ra = wm + (g & 1) * 8 + (lane & 7);
            const int ca = ks * 32 + (g >> 1) * 16;
#pragma unroll
            for (int mt = 0; mt < 4; ++mt)
                ldsm_x4(sA + sw128((uint32_t)((ra + mt * 16) * 128 + ca)), AF[mt]);
            const int rb = ks * 16 + (g & 1) * 8 + (lane & 7);
#pragma unroll
            for (int p = 0; p < 2; ++p) {
                uint32_t t[4];
                const int cbb = (wn + p * 16) * 2 + (g >> 1) * 16;
                ldsm_x4_t(sB + sw256((uint32_t)(rb * 256 + cbb)), t);
#pragma unroll
                for (int mt = 0; mt < 4; ++mt) {
                    mma16816(acc[mt][p * 2 + 0], AF[mt], t);
                    mma16816(acc[mt][p * 2 + 1], AF[mt], t + 2);
                }
            }
        }
    };

    issue(0, 0); CP_COMMIT();
    issue(1, 1); CP_COMMIT();

    int cur = 0;
    for (int kc = 0; kc < nch; ++kc) {
        CP_WAIT1();
        __syncthreads();
        compute(cur);
        if (kc + 2 < nch) {
            int nxt = cur + 2; if (nxt >= 3) nxt -= 3;
            issue(nxt, kc + 2);
        }
        CP_COMMIT();
        if (++cur == 3) cur = 0;
    }

#pragma unroll
    for (int mt = 0; mt < 4; ++mt) {
#pragma unroll
        for (int nt = 0; nt < 4; ++nt) {
            const int col = bn + wn + nt * 8 + (lane & 3) * 2;
            const float b0 = bias[col], b1 = bias[col + 1];
#pragma unroll
            for (int dp = 0; dp < 2; ++dp) {
                const int row = bm + wm + mt * 16 + (lane >> 2) + dp * 8;
                float o0 = acc[mt][nt][dp * 2 + 0] + b0;
                float o1 = acc[mt][nt][dp * 2 + 1] + b1;
                if (MODE == 1) { o0 = gelu_exact(o0); o1 = gelu_exact(o1); }
                if (MODE == 2) {
                    const float2 rv = *(const float2*)(res + (size_t)row * NN + col);
                    float2 ov; ov.x = o0 + rv.x; ov.y = o1 + rv.y;
                    *(float2*)((float*)Cout + (size_t)row * NN + col) = ov;
                } else {
                    *(__half2*)((__half*)Cout + (size_t)row * NN + col) =
                        __floats2half2_rn(o0, o1);
                }
            }
        }
    }
}

// =====================================================================
// HMMA flash attention v4 + deferred weight f2h in tail blocks.
// Blocks 0..511: attention (3-stage K/V ring, one sync/tile).
// Blocks 512..5119: f2h of wp (512) | w1 (2048) | w2 (2048) — fills the
// attention wave tail; results needed only by later GEMM launches.
// =====================================================================
#define ATT_SMEM (16384 + 3 * 16384)
#define ATT_BLOCKS 512

__global__ void __launch_bounds__(256, 2)
attn_mma(const __half* __restrict__ qkv, __half* __restrict__ o,
         const float* __restrict__ wp, __half* __restrict__ dp,
         const float* __restrict__ w1, __half* __restrict__ d1,
         const float* __restrict__ w2, __half* __restrict__ d2)
{
    const int bid = blockIdx.x;
    if (bid >= ATT_BLOCKS) {
        const int rb = bid - ATT_BLOCKS;
        if (rb < 512)       f2h_block(wp, dp, rb, threadIdx.x);
        else if (rb < 2560) f2h_block(w1, d1, rb - 512, threadIdx.x);
        else                f2h_block(w2, d2, rb - 2560, threadIdx.x);
        return;
    }

    extern __shared__ char dynsm[];
    const uint32_t Qb = smem_u32(dynsm);

    const int tid  = threadIdx.x;
    const int lane = tid & 31, wid = tid >> 5;
    const int bx = bid & 31;            // (b, head)
    const int q0 = (bid >> 5) * 128;    // q tile
    const int b = bx >> 4, hh = bx & 15;
    const size_t tb = (size_t)b * SEQ;
    const size_t RS = 3 * EMB;
    const unsigned FULL = 0xffffffffu;
    const int g = lane >> 3;
    const uint32_t ONES[2] = {0x3C003C00u, 0x3C003C00u};
    constexpr int NKT = SEQ / 64;

    auto issueKV = [&](int s, int kt) {
        const uint32_t Kb = Qb + 16384u + (uint32_t)s * 16384u;
        const uint32_t Vb = Kb + 8192u;
        const __half* kbase = qkv + (tb + kt * 64) * RS + EMB + hh * HD;
#pragma unroll
        for (int i = 0; i < 2; ++i) {
            const int cc = tid * 2 + i;
            const int r = cc >> 3, ch = cc & 7;
            const uint32_t off = sw128((uint32_t)(r * 128 + ch * 16));
            cpasync16(Kb + off, kbase + (size_t)r * RS + ch * 8);
            cpasync16(Vb + off, kbase + EMB + (size_t)r * RS + ch * 8);
        }
    };

    // ---- Q tile + prologue loads ----
    {
        const int r = tid >> 1, c0 = (tid & 1) * 32;
        const __half* qp = qkv + (tb + q0 + r) * RS + hh * HD + c0;
#pragma unroll
        for (int j = 0; j < 4; ++j)
            sts128(Qb + sw128((uint32_t)(r * 128 + (c0 + j * 8) * 2)),
                   *(const uint4*)(qp + j * 8));
    }
    issueKV(0, 0); CP_COMMIT();
    issueKV(1, 1); CP_COMMIT();
    __syncthreads();

    uint32_t QF[4][4];
#pragma unroll
    for (int t = 0; t < 4; ++t) {
        const int r = wid * 16 + (g & 1) * 8 + (lane & 7);
        const int cb = t * 32 + (g >> 1) * 16;
        ldsm_x4(Qb + sw128((uint32_t)(r * 128 + cb)), QF[t]);
    }

    float Oa[8][4];
#pragma unroll
    for (int nt = 0; nt < 8; ++nt)
#pragma unroll
        for (int c = 0; c < 4; ++c) Oa[nt][c] = 0.f;
    float lacc[4] = {0.f, 0.f, 0.f, 0.f};
    float m_run[2] = {-INFINITY, -INFINITY};

    int cur = 0;
    for (int kt = 0; kt < NKT; ++kt) {
        CP_WAIT1();
        __syncthreads();
        if (kt + 2 < NKT) {
            int nxt = cur + 2; if (nxt >= 3) nxt -= 3;
            issueKV(nxt, kt + 2);
        }
        CP_COMMIT();

        const uint32_t Kb = Qb + 16384u + (uint32_t)cur * 16384u;
        const uint32_t Vb = Kb + 8192u;

        float sacc[8][4];
#pragma unroll
        for (int nt = 0; nt < 8; ++nt)
#pragma unroll
            for (int c = 0; c < 4; ++c) sacc[nt][c] = 0.f;

#pragma unroll
        for (int t = 0; t < 4; ++t) {
#pragma unroll
            for (int pr = 0; pr < 4; ++pr) {
                const int r = pr * 16 + (g >> 1) * 8 + (lane & 7);
                const int cb = t * 32 + (g & 1) * 16;
                uint32_t tt[4];
                ldsm_x4(Kb + sw128((uint32_t)(r * 128 + cb)), tt);
                mma16816(sacc[pr * 2 + 0], QF[t], tt);
                mma16816(sacc[pr * 2 + 1], QF[t], tt + 2);
            }
        }

        float fexp[2];
#pragma unroll
        for (int ri = 0; ri < 2; ++ri) {
            float mx = sacc[0][ri * 2];
#pragma unroll
            for (int nt = 0; nt < 8; ++nt) {
                mx = fmaxf(mx, sacc[nt][ri * 2]);
                mx = fmaxf(mx, sacc[nt][ri * 2 + 1]);
            }
            mx = fmaxf(mx, __shfl_xor_sync(FULL, mx, 1));
            mx = fmaxf(mx, __shfl_xor_sync(FULL, mx, 2));
            const float mn = fmaxf(m_run[ri], mx);
            fexp[ri] = exp2f((m_run[ri] - mn) * SM_SCL);
            m_run[ri] = mn;
        }
        const float negm0 = -m_run[0] * SM_SCL;
        const float negm1 = -m_run[1] * SM_SCL;

        uint32_t P0[8], P1[8];
#pragma unroll
        for (int nt = 0; nt < 8; ++nt) {
            __half2 d0 = __floats2half2_rn(fmaf(sacc[nt][0], SM_SCL, negm0),
                                           fmaf(sacc[nt][1], SM_SCL, negm0));
            __half2 d1 = __floats2half2_rn(fmaf(sacc[nt][2], SM_SCL, negm1),
                                           fmaf(sacc[nt][3], SM_SCL, negm1));
            P0[nt] = h2u(h2exp2(d0));
            P1[nt] = h2u(h2exp2(d1));
        }

#pragma unroll
        for (int nt = 0; nt < 8; ++nt)
#pragma unroll
            for (int c = 0; c < 4; ++c)
                Oa[nt][c] *= fexp[c >> 1];
        lacc[0] *= fexp[0]; lacc[1] *= fexp[0];
        lacc[2] *= fexp[1]; lacc[3] *= fexp[1];

#pragma unroll
        for (int k2 = 0; k2 < 4; ++k2) {
            uint32_t pa[4];
            pa[0] = P0[2 * k2];     pa[1] = P1[2 * k2];
            pa[2] = P0[2 * k2 + 1]; pa[3] = P1[2 * k2 + 1];
            mma16816(lacc, pa, ONES);
#pragma unroll
            for (int npr = 0; npr < 4; ++npr) {
                const int r = k2 * 16 + (g & 1) * 8 + (lane & 7);
                const int cb = npr * 32 + (g >> 1) * 16;
                uint32_t tt[4];
                ldsm_x4_t(Vb + sw128((uint32_t)(r * 128 + cb)), tt);
                mma16816(Oa[npr * 2 + 0], pa, tt);
                mma16816(Oa[npr * 2 + 1], pa, tt + 2);
            }
        }
        if (++cur == 3) cur = 0;
    }

#pragma unroll
    for (int ri = 0; ri < 2; ++ri) {
        const int row = q0 + wid * 16 + ri * 8 + (lane >> 2);
        const float inv = 1.f / lacc[ri * 2];
#pragma unroll
        for (int nt = 0; nt < 8; ++nt) {
            const int col = nt * 8 + (lane & 3) * 2;
            *(__half2*)(o + (tb + row) * EMB + hh * HD + col) =
                __floats2half2_rn(Oa[nt][ri * 2 + 0] * inv,
                                  Oa[nt][ri * 2 + 1] * inv);
        }
    }
}

// ---------------- launch ----------------
extern "C" void kernel_launch(void* const* d_in, const int* in_sizes, int n_in,
                              void* d_out, int out_size)
{
    const float* x      = (const float*)d_in[0];
    const float* ln1_g  = (const float*)d_in[1];
    const float* ln1_b  = (const float*)d_in[2];
    const float* ln2_g  = (const float*)d_in[3];
    const float* ln2_b  = (const float*)d_in[4];
    const float* w_qkv  = (const float*)d_in[5];
    const float* b_qkv  = (const float*)d_in[6];
    const float* w_proj = (const float*)d_in[7];
    const float* b_proj = (const float*)d_in[8];
    const float* w_fc1  = (const float*)d_in[9];
    const float* b_fc1  = (const float*)d_in[10];
    const float* w_fc2  = (const float*)d_in[11];
    const float* b_fc2  = (const float*)d_in[12];
    float* out = (float*)d_out;

    void *p_h16, *p_qkv16, *p_o16, *p_act16, *p_x1;
    void *p_wq, *p_wp, *p_w1, *p_w2;
    cudaGetSymbolAddress(&p_h16, g_h16);
    cudaGetSymbolAddress(&p_qkv16, g_qkv16);
    cudaGetSymbolAddress(&p_o16, g_o16);
    cudaGetSymbolAddress(&p_act16, g_act16);
    cudaGetSymbolAddress(&p_x1, g_x1);
    cudaGetSymbolAddress(&p_wq, g_wq16);
    cudaGetSymbolAddress(&p_wp, g_wp16);
    cudaGetSymbolAddress(&p_w1, g_w116);
    cudaGetSymbolAddress(&p_w2, g_w216);
    __half* h16   = (__half*)p_h16;
    __half* qkv16 = (__half*)p_qkv16;
    __half* o16   = (__half*)p_o16;
    __half* act16 = (__half*)p_act16;
    float*  x1    = (float*)p_x1;
    __half* wq16  = (__half*)p_wq;
    __half* wp16  = (__half*)p_wp;
    __half* w116  = (__half*)p_w1;
    __half* w216  = (__half*)p_w2;

    cudaFuncSetAttribute((const void*)hgemm<0, 3 * EMB, EMB>,
                         cudaFuncAttributeMaxDynamicSharedMemorySize, GEMM_SMEM);
    cudaFuncSetAttribute((const void*)hgemm<2, EMB, EMB>,
                         cudaFuncAttributeMaxDynamicSharedMemorySize, GEMM_SMEM);
    cudaFuncSetAttribute((const void*)hgemm<1, MLP, EMB>,
                         cudaFuncAttributeMaxDynamicSharedMemorySize, GEMM_SMEM);
    cudaFuncSetAttribute((const void*)hgemm<2, EMB, MLP>,
                         cudaFuncAttributeMaxDynamicSharedMemorySize, GEMM_SMEM);
    cudaFuncSetAttribute(attn_mma, cudaFuncAttributeMaxDynamicSharedMemorySize, ATT_SMEM);

    // 0. wq f2h + LN1 (only what QKV needs)
    prep_kernel<<<1536 + TOK, 256>>>(w_qkv, wq16, x, h16, ln1_g, ln1_b);
    // 1. QKV (fp16 out)
    hgemm<0, 3 * EMB, EMB><<<dim3(3 * EMB / 128, TOK / 128), 256, GEMM_SMEM>>>(
        h16, wq16, b_qkv, nullptr, qkv16);
    // 2. attention + deferred wp/w1/w2 f2h in tail blocks
    attn_mma<<<ATT_BLOCKS + 4608, 256, ATT_SMEM>>>(qkv16, o16,
        w_proj, wp16, w_fc1, w116, w_fc2, w216);
    // 3. proj + residual (fp32 out)
    hgemm<2, EMB, EMB><<<dim3(EMB / 128, TOK / 128), 256, GEMM_SMEM>>>(
        o16, wp16, b_proj, x, x1);
    // 4. LN2 -> h16
    ln_kernel<<<TOK, 256>>>(x1, h16, ln2_g, ln2_b);
    // 5. FC1 + GELU (fp16 out)
    hgemm<1, MLP, EMB><<<dim3(MLP / 128, TOK / 128), 256, GEMM_SMEM>>>(
        h16, w116, b_fc1, nullptr, act16);
    // 6. FC2 + residual (fp32 out)
    hgemm<2, EMB, MLP><<<dim3(EMB / 128, TOK / 128), 256, GEMM_SMEM>>>(
        act16, w216, b_fc2, x1, out);
}